// round 12
// baseline (speedup 1.0000x reference)
#include <cuda_runtime.h>
#include <cstdint>

#define NTOK 4096
#define DIM  1024
#define HDIM 4096
#define NE   8

#define TM 64
#define TN 64
#define TK 16
#define PADA 132   // A-dup row: 128 floats (64 dup-pairs) + 4 pad
#define PADB 68    // B row: 64 floats + 4 pad

__device__ int   g_counts[NE];
__device__ int   g_tlist[NE * NTOK];
__device__ float g_h[(size_t)NTOK * HDIM];   // relu(x@fc)^2 scratch, 64 MB (proven-safe)

typedef unsigned long long ull;

__device__ __forceinline__ void fma2(ull& d, ull a, ull b) {
    asm("fma.rn.f32x2 %0, %1, %2, %0;" : "+l"(d) : "l"(a), "l"(b));
}
__device__ __forceinline__ float2 unpack2(ull v) {
    float2 f;
    asm("mov.b64 {%0,%1}, %2;" : "=f"(f.x), "=f"(f.y) : "l"(v));
    return f;
}

// ---------------------------------------------------------------------------
__global__ void init_counts_kernel() {
    if (threadIdx.x < NE) g_counts[threadIdx.x] = 0;
}

__global__ void router_kernel(const float* __restrict__ x,
                              const float* __restrict__ rw) {
    int warp = (blockIdx.x * blockDim.x + threadIdx.x) >> 5;
    int lane = threadIdx.x & 31;
    if (warp >= NTOK) return;
    const float* xr = x + (size_t)warp * DIM;
    float best = -1e30f;
    int bestE = 0;
#pragma unroll
    for (int e = 0; e < NE; e++) {
        const float* wr = rw + e * DIM;
        float p = 0.f;
        for (int k = lane; k < DIM; k += 32) p += xr[k] * wr[k];
#pragma unroll
        for (int o = 16; o; o >>= 1) p += __shfl_xor_sync(0xffffffffu, p, o);
        if (p > best) { best = p; bestE = e; }   // strict > => first-max (jnp.argmax)
    }
    if (lane == 0) {
        int slot = atomicAdd(&g_counts[bestE], 1);
        g_tlist[bestE * NTOK + slot] = warp;
    }
}

// ---------------------------------------------------------------------------
// Gathered grouped fp32 GEMM, R1 config (64x64x16, 256 thr, 4x4/thread),
// inner loop on fma.rn.f32x2 with A stored as duplicated pairs in smem.
// BTRANS=true : B elem (k,n) at Bq[k*HDIM+n]  (GEMM1, fc)   -> direct row copy
// BTRANS=false: B elem (n,k) at Bq[n*HDIM+k]  (GEMM2, proj) -> transpose on store
template <int KTOT, bool RELU2, bool BTRANS>
__global__ __launch_bounds__(256) void gemm_f32x2(
    const float* __restrict__ Abase, int astride,
    const float* __restrict__ Bbase,
    float* __restrict__ Obase, int ostride)
{
    constexpr int KT = KTOT / TK;

    __shared__ int   toks[TM];
    __shared__ float Asd[2][TK][PADA];   // [k][2*m]: (a_m, a_m) pairs
    __shared__ float Bs[2][TK][PADB];    // [k][n]

    const int e = blockIdx.z;
    const int count = g_counts[e];
    const int m0 = blockIdx.y * TM;
    if (m0 >= count) return;
    const int n0 = blockIdx.x * TN;

    const int tid = threadIdx.x;
    if (tid < TM) {
        int mg = m0 + tid;
        toks[tid] = (mg < count) ? g_tlist[e * NTOK + mg] : -1;
    }
    __syncthreads();

    const float* Bq = Bbase + (size_t)e * DIM * HDIM;

    // ---- loader mappings (R1-proven): one float4 per thread per operand ----
    const int arow = tid >> 2;             // 0..63
    const int akq  = (tid & 3) * 4;        // 0,4,8,12
    const int atok = toks[arow];
    const float* aptr = (atok >= 0) ? (Abase + (size_t)atok * astride + akq) : nullptr;

    const float* bptr;
    int bkk = 0, bn4 = 0, brow = 0, bkq = 0;
    if (BTRANS) {                          // tile [k=16][n=64]
        bkk = tid >> 4;                    // 0..15
        bn4 = (tid & 15) * 4;              // 0..60
        bptr = Bq + (size_t)bkk * HDIM + n0 + bn4;
    } else {                               // src [n][k] -> transpose on store
        brow = tid >> 2;                   // 0..63
        bkq  = (tid & 3) * 4;
        bptr = Bq + (size_t)(n0 + brow) * HDIM + bkq;
    }

    float4 ra, rb;
    auto LOAD = [&](int k0) {
        ra = aptr ? *(const float4*)(aptr + k0) : make_float4(0.f, 0.f, 0.f, 0.f);
        if (BTRANS) rb = *(const float4*)(bptr + (size_t)k0 * HDIM);
        else        rb = *(const float4*)(bptr + k0);
    };
    auto STORE = [&](int s) {
        // A: duplicate each value into a pair at [k][2*row]
        *(float2*)&Asd[s][akq + 0][2 * arow] = make_float2(ra.x, ra.x);
        *(float2*)&Asd[s][akq + 1][2 * arow] = make_float2(ra.y, ra.y);
        *(float2*)&Asd[s][akq + 2][2 * arow] = make_float2(ra.z, ra.z);
        *(float2*)&Asd[s][akq + 3][2 * arow] = make_float2(ra.w, ra.w);
        if (BTRANS) {
            *(float4*)&Bs[s][bkk][bn4] = rb;
        } else {
            Bs[s][bkq + 0][brow] = rb.x;
            Bs[s][bkq + 1][brow] = rb.y;
            Bs[s][bkq + 2][brow] = rb.z;
            Bs[s][bkq + 3][brow] = rb.w;
        }
    };

    const int tx = tid & 15;               // cols tx*4..+3
    const int ty = tid >> 4;               // rows ty*4..+3

    ull acc[4][2];                          // [row][colpair]
#pragma unroll
    for (int i = 0; i < 4; i++) { acc[i][0] = 0ull; acc[i][1] = 0ull; }

    LOAD(0);
    STORE(0);
    __syncthreads();

    for (int kt = 0; kt < KT; kt++) {
        const int s = kt & 1;
        if (kt + 1 < KT) LOAD((kt + 1) * TK);

#pragma unroll
        for (int kk = 0; kk < TK; kk++) {
            // A dup-pairs: rows ty*4..+3 -> 32B at float index 8*ty (2-addr broadcast/warp)
            ulonglong2 aq0 = *(const ulonglong2*)&Asd[s][kk][8 * ty];      // rows 0,1
            ulonglong2 aq1 = *(const ulonglong2*)&Asd[s][kk][8 * ty + 4];  // rows 2,3
            // B: 16B contiguous per lane group (conflict-free)
            ulonglong2 bq = *(const ulonglong2*)&Bs[s][kk][tx * 4];        // colpairs 0,1
            fma2(acc[0][0], aq0.x, bq.x); fma2(acc[0][1], aq0.x, bq.y);
            fma2(acc[1][0], aq0.y, bq.x); fma2(acc[1][1], aq0.y, bq.y);
            fma2(acc[2][0], aq1.x, bq.x); fma2(acc[2][1], aq1.x, bq.y);
            fma2(acc[3][0], aq1.y, bq.x); fma2(acc[3][1], aq1.y, bq.y);
        }

        if (kt + 1 < KT) {
            __syncthreads();
            STORE(s ^ 1);
            __syncthreads();
        }
    }

    // ---- epilogue (R1 positions) ----
#pragma unroll
    for (int i = 0; i < 4; i++) {
        int tok = toks[ty * 4 + i];
        if (tok < 0) continue;
        float2 p0 = unpack2(acc[i][0]);
        float2 p1 = unpack2(acc[i][1]);
        float4 v = make_float4(p0.x, p0.y, p1.x, p1.y);
        if (RELU2) {
            v.x = fmaxf(v.x, 0.f); v.x *= v.x;
            v.y = fmaxf(v.y, 0.f); v.y *= v.y;
            v.z = fmaxf(v.z, 0.f); v.z *= v.z;
            v.w = fmaxf(v.w, 0.f); v.w *= v.w;
        }
        *(float4*)(Obase + (size_t)tok * ostride + n0 + tx * 4) = v;
    }
}

// ---------------------------------------------------------------------------
extern "C" void kernel_launch(void* const* d_in, const int* in_sizes, int n_in,
                              void* d_out, int out_size) {
    const float* x    = (const float*)d_in[0];
    const float* rw   = (const float*)d_in[1];
    const float* fc   = (const float*)d_in[2];
    const float* proj = (const float*)d_in[3];
    float* out = (float*)d_out;

    init_counts_kernel<<<1, 32>>>();
    router_kernel<<<(NTOK * 32) / 256, 256>>>(x, rw);

    dim3 g1(HDIM / TN, NTOK / TM, NE);   // 64 x 64 x 8, most blocks early-exit
    gemm_f32x2<DIM, true, true><<<g1, 256>>>(x, DIM, fc, g_h, HDIM);

    dim3 g2(DIM / TN, NTOK / TM, NE);    // 16 x 64 x 8
    gemm_f32x2<HDIM, false, false><<<g2, 256>>>(g_h, HDIM, proj, out, DIM);
}

// round 13
// speedup vs baseline: 1.0088x; 1.0088x over previous
#include <cuda_runtime.h>
#include <cstdint>

#define NTOK 4096
#define DIM  1024
#define HDIM 4096
#define NE   8

#define TM 128
#define TN 64
#define TK 16
#define PADA 132   // As row stride (floats)
#define PADB 68    // Bs row stride (floats)

__device__ int   g_counts[NE];
__device__ int   g_tlist[NE * NTOK];
__device__ float g_h[(size_t)NTOK * HDIM];   // relu(x@fc)^2 scratch, 64 MB (proven-safe)

// ---------------------------------------------------------------------------
__global__ void init_counts_kernel() {
    if (threadIdx.x < NE) g_counts[threadIdx.x] = 0;
}

__global__ void router_kernel(const float* __restrict__ x,
                              const float* __restrict__ rw) {
    int warp = (blockIdx.x * blockDim.x + threadIdx.x) >> 5;
    int lane = threadIdx.x & 31;
    if (warp >= NTOK) return;
    const float* xr = x + (size_t)warp * DIM;
    float best = -1e30f;
    int bestE = 0;
#pragma unroll
    for (int e = 0; e < NE; e++) {
        const float* wr = rw + e * DIM;
        float p = 0.f;
        for (int k = lane; k < DIM; k += 32) p += xr[k] * wr[k];
#pragma unroll
        for (int o = 16; o; o >>= 1) p += __shfl_xor_sync(0xffffffffu, p, o);
        if (p > best) { best = p; bestE = e; }   // strict > => first-max (jnp.argmax)
    }
    if (lane == 0) {
        int slot = atomicAdd(&g_counts[bestE], 1);
        g_tlist[bestE * NTOK + slot] = warp;
    }
}

// ---------------------------------------------------------------------------
// Gathered grouped fp32 SIMT GEMM (R1 core scaled to 128x64, 8x4 per thread).
// smem: As[k][m], Bs[k][n].
// BTRANS=true : B elem (k,n) at Bq[k*HDIM+n]  (GEMM1, fc)   -> direct row copy
// BTRANS=false: B elem (n,k) at Bq[n*HDIM+k]  (GEMM2, proj) -> transpose on store
template <int KTOT, bool RELU2, bool BTRANS>
__global__ __launch_bounds__(256) void gemm_simt(
    const float* __restrict__ Abase, int astride,
    const float* __restrict__ Bbase,
    float* __restrict__ Obase, int ostride)
{
    constexpr int KT = KTOT / TK;

    __shared__ int   toks[TM];
    __shared__ float As[2][TK][PADA];
    __shared__ float Bs[2][TK][PADB];

    const int e = blockIdx.z;
    const int count = g_counts[e];
    const int m0 = blockIdx.y * TM;
    if (m0 >= count) return;
    const int n0 = blockIdx.x * TN;

    const int tid = threadIdx.x;
    if (tid < TM) {
        int mg = m0 + tid;
        toks[tid] = (mg < count) ? g_tlist[e * NTOK + mg] : -1;
    }
    __syncthreads();

    const float* Bq = Bbase + (size_t)e * DIM * HDIM;

    // ---- A loader: 128 rows x 16 k = 512 float4; 2 slots/thread (R1 algebra) ----
    const float* aptr[2];
    int arow[2], akq[2];
#pragma unroll
    for (int q = 0; q < 2; q++) {
        int idx = q * 256 + tid;
        arow[q] = idx >> 2;                 // 0..127
        akq[q]  = (idx & 3) * 4;            // 0,4,8,12
        int tok = toks[arow[q]];
        aptr[q] = (tok >= 0) ? (Abase + (size_t)tok * astride + akq[q]) : nullptr;
    }
    // ---- B loader: 64 rows/cols as in R1 ----
    const float* bptr;
    int bkk = 0, bn4 = 0, brow = 0, bkq = 0;
    if (BTRANS) {                           // tile [k=16][n=64]
        bkk = tid >> 4;                     // 0..15
        bn4 = (tid & 15) * 4;               // 0..60
        bptr = Bq + (size_t)bkk * HDIM + n0 + bn4;
    } else {                                // src [n][k] -> transpose on store
        brow = tid >> 2;                    // 0..63
        bkq  = (tid & 3) * 4;
        bptr = Bq + (size_t)(n0 + brow) * HDIM + bkq;
    }

    float4 ra[2], rb;
    auto LOAD = [&](int k0) {
#pragma unroll
        for (int q = 0; q < 2; q++)
            ra[q] = aptr[q] ? *(const float4*)(aptr[q] + k0)
                            : make_float4(0.f, 0.f, 0.f, 0.f);
        if (BTRANS) rb = *(const float4*)(bptr + (size_t)k0 * HDIM);
        else        rb = *(const float4*)(bptr + k0);
    };
    auto STORE = [&](int s) {
#pragma unroll
        for (int q = 0; q < 2; q++) {
            As[s][akq[q] + 0][arow[q]] = ra[q].x;
            As[s][akq[q] + 1][arow[q]] = ra[q].y;
            As[s][akq[q] + 2][arow[q]] = ra[q].z;
            As[s][akq[q] + 3][arow[q]] = ra[q].w;
        }
        if (BTRANS) {
            *(float4*)&Bs[s][bkk][bn4] = rb;
        } else {
            Bs[s][bkq + 0][brow] = rb.x;
            Bs[s][bkq + 1][brow] = rb.y;
            Bs[s][bkq + 2][brow] = rb.z;
            Bs[s][bkq + 3][brow] = rb.w;
        }
    };

    const int tx = tid & 15;                // cols n0 + tx*4..+3
    const int ty = tid >> 4;                // rows ty*8..+7

    float acc[8][4];
#pragma unroll
    for (int i = 0; i < 8; i++)
#pragma unroll
        for (int j = 0; j < 4; j++) acc[i][j] = 0.f;

    LOAD(0);
    STORE(0);
    __syncthreads();

    for (int kt = 0; kt < KT; kt++) {
        const int s = kt & 1;
        if (kt + 1 < KT) LOAD((kt + 1) * TK);

#pragma unroll
        for (int kk = 0; kk < TK; kk++) {
            float4 a0 = *(const float4*)&As[s][kk][ty * 8];       // rows 0..3
            float4 a1 = *(const float4*)&As[s][kk][ty * 8 + 4];   // rows 4..7
            float4 b  = *(const float4*)&Bs[s][kk][tx * 4];
            acc[0][0] += a0.x * b.x; acc[0][1] += a0.x * b.y; acc[0][2] += a0.x * b.z; acc[0][3] += a0.x * b.w;
            acc[1][0] += a0.y * b.x; acc[1][1] += a0.y * b.y; acc[1][2] += a0.y * b.z; acc[1][3] += a0.y * b.w;
            acc[2][0] += a0.z * b.x; acc[2][1] += a0.z * b.y; acc[2][2] += a0.z * b.z; acc[2][3] += a0.z * b.w;
            acc[3][0] += a0.w * b.x; acc[3][1] += a0.w * b.y; acc[3][2] += a0.w * b.z; acc[3][3] += a0.w * b.w;
            acc[4][0] += a1.x * b.x; acc[4][1] += a1.x * b.y; acc[4][2] += a1.x * b.z; acc[4][3] += a1.x * b.w;
            acc[5][0] += a1.y * b.x; acc[5][1] += a1.y * b.y; acc[5][2] += a1.y * b.z; acc[5][3] += a1.y * b.w;
            acc[6][0] += a1.z * b.x; acc[6][1] += a1.z * b.y; acc[6][2] += a1.z * b.z; acc[6][3] += a1.z * b.w;
            acc[7][0] += a1.w * b.x; acc[7][1] += a1.w * b.y; acc[7][2] += a1.w * b.z; acc[7][3] += a1.w * b.w;
        }

        if (kt + 1 < KT) {
            __syncthreads();
            STORE(s ^ 1);
            __syncthreads();
        }
    }

    // ---- epilogue (R1 pattern, 8 rows) ----
#pragma unroll
    for (int i = 0; i < 8; i++) {
        int tok = toks[ty * 8 + i];
        if (tok < 0) continue;
        float4 v = make_float4(acc[i][0], acc[i][1], acc[i][2], acc[i][3]);
        if (RELU2) {
            v.x = fmaxf(v.x, 0.f); v.x *= v.x;
            v.y = fmaxf(v.y, 0.f); v.y *= v.y;
            v.z = fmaxf(v.z, 0.f); v.z *= v.z;
            v.w = fmaxf(v.w, 0.f); v.w *= v.w;
        }
        *(float4*)(Obase + (size_t)tok * ostride + n0 + tx * 4) = v;
    }
}

// ---------------------------------------------------------------------------
extern "C" void kernel_launch(void* const* d_in, const int* in_sizes, int n_in,
                              void* d_out, int out_size) {
    const float* x    = (const float*)d_in[0];
    const float* rw   = (const float*)d_in[1];
    const float* fc   = (const float*)d_in[2];
    const float* proj = (const float*)d_in[3];
    float* out = (float*)d_out;

    init_counts_kernel<<<1, 32>>>();
    router_kernel<<<(NTOK * 32) / 256, 256>>>(x, rw);

    dim3 g1(HDIM / TN, NTOK / TM, NE);   // 64 x 32 x 8, most blocks early-exit
    gemm_simt<DIM, true, true><<<g1, 256>>>(x, DIM, fc, g_h, HDIM);

    dim3 g2(DIM / TN, NTOK / TM, NE);    // 16 x 32 x 8
    gemm_simt<HDIM, false, false><<<g2, 256>>>(g_h, HDIM, proj, out, DIM);
}

// round 14
// speedup vs baseline: 2.9089x; 2.8835x over previous
#include <cuda_runtime.h>

#define NTOK 4096
#define DIM  1024
#define HDIM 4096
#define NE   8

#define TM 64
#define TN 64
#define TK 16
#define SSTRIDE 68   // smem row stride (floats): keeps 16B alignment, reduces conflicts

__device__ int   g_counts[NE];
__device__ int   g_tlist[NE * NTOK];
__device__ float g_h[(size_t)NTOK * HDIM];   // relu(x@fc)^2 scratch, 64 MB

// ---------------------------------------------------------------------------
__global__ void init_counts_kernel() {
    if (threadIdx.x < NE) g_counts[threadIdx.x] = 0;
}

// One warp per token: fp32 logits, first-max argmax (matches jnp.argmax),
// atomic compaction into per-expert token lists.
__global__ void router_kernel(const float* __restrict__ x,
                              const float* __restrict__ rw) {
    int warp = (blockIdx.x * blockDim.x + threadIdx.x) >> 5;
    int lane = threadIdx.x & 31;
    if (warp >= NTOK) return;
    const float* xr = x + (size_t)warp * DIM;
    float best = -1e30f;
    int bestE = 0;
#pragma unroll
    for (int e = 0; e < NE; e++) {
        const float* wr = rw + e * DIM;
        float p = 0.f;
        for (int k = lane; k < DIM; k += 32) p += xr[k] * wr[k];
#pragma unroll
        for (int o = 16; o; o >>= 1) p += __shfl_xor_sync(0xffffffffu, p, o);
        if (p > best) { best = p; bestE = e; }   // strict > keeps earliest index
    }
    if (lane == 0) {
        int slot = atomicAdd(&g_counts[bestE], 1);
        g_tlist[bestE * NTOK + slot] = warp;
    }
}

// ---------------------------------------------------------------------------
// GEMM1: for expert e, h[token, n] = relu( x[token,:] @ fc_e[:, n] )^2
// fc layout [E, D, HD] (n contiguous). A rows gathered via token list.
__global__ __launch_bounds__(256) void gemm1_kernel(const float* __restrict__ x,
                                                    const float* __restrict__ fc) {
    const int e = blockIdx.z;
    const int count = g_counts[e];
    const int m0 = blockIdx.y * TM;
    if (m0 >= count) return;
    const int n0 = blockIdx.x * TN;

    __shared__ float As[TK][SSTRIDE];   // transposed: As[k][row]
    __shared__ float Bs[TK][SSTRIDE];   // Bs[k][col]
    __shared__ int   toks[TM];

    const int tid = threadIdx.x;
    const int tx = tid & 15;            // 16 col groups
    const int ty = tid >> 4;            // 16 row groups

    if (tid < TM) {
        int mg = m0 + tid;
        toks[tid] = (mg < count) ? g_tlist[e * NTOK + mg] : -1;
    }
    __syncthreads();

    // A-load mapping: row = tid/4, kg = tid%4 -> k = kg*4 (float4)
    const int a_row = tid >> 2;
    const int a_k   = (tid & 3) * 4;
    // B-load mapping: k = tid/16, ng = tid%16 -> n = ng*4 (float4)
    const int b_k = tid >> 4;
    const int b_n = (tid & 15) * 4;

    const float* fce = fc + (size_t)e * DIM * HDIM;

    float acc[4][4];
#pragma unroll
    for (int i = 0; i < 4; i++)
#pragma unroll
        for (int j = 0; j < 4; j++) acc[i][j] = 0.f;

    const int tokA = toks[a_row];

    for (int k0 = 0; k0 < DIM; k0 += TK) {
        // load A tile (gathered, transposed into smem)
        float4 av = make_float4(0.f, 0.f, 0.f, 0.f);
        if (tokA >= 0)
            av = *(const float4*)(x + (size_t)tokA * DIM + k0 + a_k);
        As[a_k + 0][a_row] = av.x;
        As[a_k + 1][a_row] = av.y;
        As[a_k + 2][a_row] = av.z;
        As[a_k + 3][a_row] = av.w;
        // load B tile
        float4 bv = *(const float4*)(fce + (size_t)(k0 + b_k) * HDIM + n0 + b_n);
        *(float4*)&Bs[b_k][b_n] = bv;
        __syncthreads();

#pragma unroll
        for (int kk = 0; kk < TK; kk++) {
            float4 a = *(const float4*)&As[kk][ty * 4];
            float4 b = *(const float4*)&Bs[kk][tx * 4];
            acc[0][0] += a.x * b.x; acc[0][1] += a.x * b.y; acc[0][2] += a.x * b.z; acc[0][3] += a.x * b.w;
            acc[1][0] += a.y * b.x; acc[1][1] += a.y * b.y; acc[1][2] += a.y * b.z; acc[1][3] += a.y * b.w;
            acc[2][0] += a.z * b.x; acc[2][1] += a.z * b.y; acc[2][2] += a.z * b.z; acc[2][3] += a.z * b.w;
            acc[3][0] += a.w * b.x; acc[3][1] += a.w * b.y; acc[3][2] += a.w * b.z; acc[3][3] += a.w * b.w;
        }
        __syncthreads();
    }

#pragma unroll
    for (int i = 0; i < 4; i++) {
        int r = ty * 4 + i;
        int tok = toks[r];
        if (tok < 0) continue;
        float4 v;
        float t0 = fmaxf(acc[i][0], 0.f);
        float t1 = fmaxf(acc[i][1], 0.f);
        float t2 = fmaxf(acc[i][2], 0.f);
        float t3 = fmaxf(acc[i][3], 0.f);
        v.x = t0 * t0; v.y = t1 * t1; v.z = t2 * t2; v.w = t3 * t3;
        *(float4*)(g_h + (size_t)tok * HDIM + n0 + tx * 4) = v;
    }
}

// ---------------------------------------------------------------------------
// GEMM2: out[token, d] = h[token,:] @ proj_e[d, :]   (proj layout [E, D, HD], k=h contiguous)
__global__ __launch_bounds__(256) void gemm2_kernel(const float* __restrict__ proj,
                                                    float* __restrict__ out) {
    const int e = blockIdx.z;
    const int count = g_counts[e];
    const int m0 = blockIdx.y * TM;
    if (m0 >= count) return;
    const int n0 = blockIdx.x * TN;

    __shared__ float As[TK][SSTRIDE];
    __shared__ float Bs[TK][SSTRIDE];
    __shared__ int   toks[TM];

    const int tid = threadIdx.x;
    const int tx = tid & 15;
    const int ty = tid >> 4;

    if (tid < TM) {
        int mg = m0 + tid;
        toks[tid] = (mg < count) ? g_tlist[e * NTOK + mg] : -1;
    }
    __syncthreads();

    const int a_row = tid >> 2;
    const int a_k   = (tid & 3) * 4;
    // B: n-major rows, k contiguous -> load [n, k..k+3] and transpose into smem
    const int b_n  = tid >> 2;          // 64 n values
    const int b_k  = (tid & 3) * 4;     // 4 k groups

    const float* pe = proj + (size_t)e * DIM * HDIM;

    float acc[4][4];
#pragma unroll
    for (int i = 0; i < 4; i++)
#pragma unroll
        for (int j = 0; j < 4; j++) acc[i][j] = 0.f;

    const int tokA = toks[a_row];

    for (int k0 = 0; k0 < HDIM; k0 += TK) {
        float4 av = make_float4(0.f, 0.f, 0.f, 0.f);
        if (tokA >= 0)
            av = *(const float4*)(g_h + (size_t)tokA * HDIM + k0 + a_k);
        As[a_k + 0][a_row] = av.x;
        As[a_k + 1][a_row] = av.y;
        As[a_k + 2][a_row] = av.z;
        As[a_k + 3][a_row] = av.w;

        float4 bv = *(const float4*)(pe + (size_t)(n0 + b_n) * HDIM + k0 + b_k);
        Bs[b_k + 0][b_n] = bv.x;
        Bs[b_k + 1][b_n] = bv.y;
        Bs[b_k + 2][b_n] = bv.z;
        Bs[b_k + 3][b_n] = bv.w;
        __syncthreads();

#pragma unroll
        for (int kk = 0; kk < TK; kk++) {
            float4 a = *(const float4*)&As[kk][ty * 4];
            float4 b = *(const float4*)&Bs[kk][tx * 4];
            acc[0][0] += a.x * b.x; acc[0][1] += a.x * b.y; acc[0][2] += a.x * b.z; acc[0][3] += a.x * b.w;
            acc[1][0] += a.y * b.x; acc[1][1] += a.y * b.y; acc[1][2] += a.y * b.z; acc[1][3] += a.y * b.w;
            acc[2][0] += a.z * b.x; acc[2][1] += a.z * b.y; acc[2][2] += a.z * b.z; acc[2][3] += a.z * b.w;
            acc[3][0] += a.w * b.x; acc[3][1] += a.w * b.y; acc[3][2] += a.w * b.z; acc[3][3] += a.w * b.w;
        }
        __syncthreads();
    }

#pragma unroll
    for (int i = 0; i < 4; i++) {
        int r = ty * 4 + i;
        int tok = toks[r];
        if (tok < 0) continue;
        float4 v = make_float4(acc[i][0], acc[i][1], acc[i][2], acc[i][3]);
        *(float4*)(out + (size_t)tok * DIM + n0 + tx * 4) = v;
    }
}

// ---------------------------------------------------------------------------
extern "C" void kernel_launch(void* const* d_in, const int* in_sizes, int n_in,
                              void* d_out, int out_size) {
    const float* x    = (const float*)d_in[0];
    const float* rw   = (const float*)d_in[1];
    const float* fc   = (const float*)d_in[2];
    const float* proj = (const float*)d_in[3];
    float* out = (float*)d_out;

    init_counts_kernel<<<1, 32>>>();
    router_kernel<<<(NTOK * 32) / 256, 256>>>(x, rw);

    dim3 g1(HDIM / TN, NTOK / TM, NE);   // 64 x 64 x 8, most blocks early-exit
    gemm1_kernel<<<g1, 256>>>(x, fc);

    dim3 g2(DIM / TN, NTOK / TM, NE);    // 16 x 64 x 8
    gemm2_kernel<<<g2, 256>>>(proj, out);
}